// round 1
// baseline (speedup 1.0000x reference)
#include <cuda_runtime.h>

// KernelNorm2d: kernel=2x2, stride=2, pad=0  ->  identity spatial mapping.
// out[b,c,h,w] = (x[b,c,h,w] - mu[b,h/2,w/2]) * rsqrt(var[b,h/2,w/2] + eps)
// group = 64 channels x 2x2 pixels = 256 values per window.

#define BB 16
#define CC 64
#define HH 256
#define WW 256
#define EPSV 1e-5f

// One CTA per (b, i) row-pair. 512 threads:
//   j4 = t & 63  -> float4 column group (windows 2*j4, 2*j4+1)
//   cg = t >> 6  -> 8 channels
// Each thread: 16 x LDG.128 held in registers, smem reduce over the 8
// channel-group threads per window, normalize from regs, 16 x STG.128.
__global__ __launch_bounds__(512, 1)
void knorm2d_kernel(const float* __restrict__ x, float* __restrict__ y) {
    const int bi = blockIdx.x;
    const int b  = bi >> 7;       // / 128
    const int i  = bi & 127;      // row-pair index
    const int t  = threadIdx.x;
    const int j4 = t & 63;
    const int cg = t >> 6;        // channel group 0..7 (8 channels each)

    const float4* __restrict__ xb = reinterpret_cast<const float4*>(x);
    float4* __restrict__ yb = reinterpret_cast<float4*>(y);

    // float4 element index: ((b*CC + c)*HH + h)*(WW/4) + j4
    const long chanStride4 = (long)HH * (WW / 4);           // 16384
    const long base = ((long)(b * CC + cg * 8) * HH + 2 * i) * (WW / 4) + j4;

    float4 v[16];
#pragma unroll
    for (int cc = 0; cc < 8; ++cc) {
#pragma unroll
        for (int r = 0; r < 2; ++r) {
            v[cc * 2 + r] = xb[base + (long)cc * chanStride4 + r * (WW / 4)];
        }
    }

    // Partial sums: window A = (x,y) lanes, window B = (z,w) lanes
    float sA = 0.f, ssA = 0.f, sB = 0.f, ssB = 0.f;
#pragma unroll
    for (int k = 0; k < 16; ++k) {
        const float4 q = v[k];
        sA  += q.x + q.y;
        ssA  = fmaf(q.x, q.x, fmaf(q.y, q.y, ssA));
        sB  += q.z + q.w;
        ssB  = fmaf(q.z, q.z, fmaf(q.w, q.w, ssB));
    }

    __shared__ float4 red[512];
    red[t] = make_float4(sA, ssA, sB, ssB);
    __syncthreads();

    float SA = 0.f, SSA = 0.f, SB = 0.f, SSB = 0.f;
#pragma unroll
    for (int k = 0; k < 8; ++k) {
        const float4 q = red[(k << 6) | j4];
        SA += q.x; SSA += q.y; SB += q.z; SSB += q.w;
    }

    const float inv = 1.0f / 256.0f;
    const float muA = SA * inv;
    const float muB = SB * inv;
    const float varA = fmaf(-muA, muA, SSA * inv);
    const float varB = fmaf(-muB, muB, SSB * inv);
    const float rA = rsqrtf(varA + EPSV);
    const float rB = rsqrtf(varB + EPSV);

#pragma unroll
    for (int cc = 0; cc < 8; ++cc) {
#pragma unroll
        for (int r = 0; r < 2; ++r) {
            float4 q = v[cc * 2 + r];
            q.x = (q.x - muA) * rA;
            q.y = (q.y - muA) * rA;
            q.z = (q.z - muB) * rB;
            q.w = (q.w - muB) * rB;
            yb[base + (long)cc * chanStride4 + r * (WW / 4)] = q;
        }
    }
}

extern "C" void kernel_launch(void* const* d_in, const int* in_sizes, int n_in,
                              void* d_out, int out_size) {
    const float* x = (const float*)d_in[0];
    float* y = (float*)d_out;
    knorm2d_kernel<<<BB * 128, 512>>>(x, y);
}

// round 3
// speedup vs baseline: 1.0252x; 1.0252x over previous
#include <cuda_runtime.h>

// KernelNorm2d: kernel=2x2, stride=2, pad=0 -> identity spatial mapping.
// out[b,c,h,w] = (x[b,c,h,w] - mu[b,h/2,w/2]) * rsqrt(var[b,h/2,w/2] + eps)
// group = 64 channels x 2x2 pixels = 256 values per window.
//
// One CTA per (b, row-pair i). 512 threads, 16 warps. Lane mapping puts the
// 8 reduction partners of each window inside one warp:
//   cg  = lane >> 2            (8 channel-groups, 8 channels each)
//   j4  = warp*4 + (lane & 3)  (float4 column group -> windows 2*j4, 2*j4+1)
// Reduction = 3x shfl_xor (4/8/16). No smem, no __syncthreads -> warps are
// fully independent pipelines; loads/stores of different warps overlap.

#define EPSV 1e-5f

__global__ __launch_bounds__(512, 1)
void knorm2d_kernel(const float* __restrict__ x, float* __restrict__ y) {
    const int bi   = blockIdx.x;
    const int b    = bi >> 7;          // batch
    const int i    = bi & 127;         // row-pair
    const int t    = threadIdx.x;
    const int lane = t & 31;
    const int warp = t >> 5;
    const int cg   = lane >> 2;                 // channel group 0..7
    const int j4   = (warp << 2) | (lane & 3);  // column float4 group 0..63

    const float4* __restrict__ xb = reinterpret_cast<const float4*>(x);
    float4* __restrict__ yb = reinterpret_cast<float4*>(y);

    // float4 index: ((b*64 + c)*256 + h)*64 + j4   (max ~16.7M, fits int32)
    const int chanStride4 = 256 * 64;  // 16384
    const int base = ((b * 64 + cg * 8) * 256 + 2 * i) * 64 + j4;

    float4 v[16];
#pragma unroll
    for (int cc = 0; cc < 8; ++cc) {
#pragma unroll
        for (int r = 0; r < 2; ++r) {
            v[cc * 2 + r] = xb[base + cc * chanStride4 + r * 64];
        }
    }

    // Partial sums: window A = (x,y) lanes, window B = (z,w) lanes
    float sA = 0.f, ssA = 0.f, sB = 0.f, ssB = 0.f;
#pragma unroll
    for (int k = 0; k < 16; ++k) {
        const float4 q = v[k];
        sA += q.x + q.y;
        ssA = fmaf(q.x, q.x, fmaf(q.y, q.y, ssA));
        sB += q.z + q.w;
        ssB = fmaf(q.z, q.z, fmaf(q.w, q.w, ssB));
    }

    // Reduce across the 8 channel-group lanes (lane bits 2..4)
#pragma unroll
    for (int m = 4; m <= 16; m <<= 1) {
        sA  += __shfl_xor_sync(0xFFFFFFFFu, sA,  m);
        ssA += __shfl_xor_sync(0xFFFFFFFFu, ssA, m);
        sB  += __shfl_xor_sync(0xFFFFFFFFu, sB,  m);
        ssB += __shfl_xor_sync(0xFFFFFFFFu, ssB, m);
    }

    const float inv = 1.0f / 256.0f;
    const float muA = sA * inv;
    const float muB = sB * inv;
    const float varA = fmaf(-muA, muA, ssA * inv);
    const float varB = fmaf(-muB, muB, ssB * inv);
    const float rA = rsqrtf(varA + EPSV);
    const float rB = rsqrtf(varB + EPSV);

#pragma unroll
    for (int cc = 0; cc < 8; ++cc) {
#pragma unroll
        for (int r = 0; r < 2; ++r) {
            float4 q = v[cc * 2 + r];
            q.x = (q.x - muA) * rA;
            q.y = (q.y - muA) * rA;
            q.z = (q.z - muB) * rB;
            q.w = (q.w - muB) * rB;
            yb[base + cc * chanStride4 + r * 64] = q;
        }
    }
}

extern "C" void kernel_launch(void* const* d_in, const int* in_sizes, int n_in,
                              void* d_out, int out_size) {
    const float* x = (const float*)d_in[0];
    float* y = (float*)d_out;
    knorm2d_kernel<<<16 * 128, 512>>>(x, y);
}

// round 4
// speedup vs baseline: 1.0447x; 1.0190x over previous
#include <cuda_runtime.h>

// KernelNorm2d: kernel=2x2, stride=2, pad=0 -> identity spatial mapping.
// out[b,c,h,w] = (x[b,c,h,w] - mu[b,h/2,w/2]) * rsqrt(var[b,h/2,w/2] + eps)
// group = 64 channels x 2x2 pixels = 256 values per window.
//
// 256-thread CTAs (8 warps), 4+ CTAs/SM for phase overlap across CTAs.
// Warp covers 2 float4-cols x 64 channels x 2 rows:
//   cg = lane >> 1  (16 channel-groups, 4 channels each)
//   jj = lane & 1   (float4-col within warp)
// Thread holds 8 float4 in regs; window sums reduced with 4x shfl_xor
// (masks 2/4/8/16). No smem, no barriers.

#define EPSV 1e-5f

__global__ __launch_bounds__(256, 4)
void knorm2d_kernel(const float* __restrict__ x, float* __restrict__ y) {
    const int bid  = blockIdx.x;
    const int cblk = bid & 3;          // column block 0..3 (16 float4-cols each)
    const int i    = (bid >> 2) & 127; // row-pair
    const int b    = bid >> 9;         // batch
    const int t    = threadIdx.x;
    const int lane = t & 31;
    const int warp = t >> 5;           // 0..7
    const int cg   = lane >> 1;        // channel group 0..15 (4 channels each)
    const int j4   = (cblk << 4) | (warp << 1) | (lane & 1);  // float4-col 0..63

    const float4* __restrict__ xb = reinterpret_cast<const float4*>(x);
    float4* __restrict__ yb = reinterpret_cast<float4*>(y);

    // float4 index: ((b*64 + c)*256 + h)*64 + j4   (max ~16.7M, fits int32)
    const int chanStride4 = 256 * 64;  // 16384
    const int base = ((b * 64 + cg * 4) * 256 + 2 * i) * 64 + j4;

    float4 v[8];
#pragma unroll
    for (int cc = 0; cc < 4; ++cc) {
#pragma unroll
        for (int r = 0; r < 2; ++r) {
            v[cc * 2 + r] = xb[base + cc * chanStride4 + r * 64];
        }
    }

    // Partial sums: window A = (x,y) lanes, window B = (z,w) lanes
    float sA = 0.f, ssA = 0.f, sB = 0.f, ssB = 0.f;
#pragma unroll
    for (int k = 0; k < 8; ++k) {
        const float4 q = v[k];
        sA += q.x + q.y;
        ssA = fmaf(q.x, q.x, fmaf(q.y, q.y, ssA));
        sB += q.z + q.w;
        ssB = fmaf(q.z, q.z, fmaf(q.w, q.w, ssB));
    }

    // Reduce across the 16 channel-group lanes (lane bits 1..4)
#pragma unroll
    for (int m = 2; m <= 16; m <<= 1) {
        sA  += __shfl_xor_sync(0xFFFFFFFFu, sA,  m);
        ssA += __shfl_xor_sync(0xFFFFFFFFu, ssA, m);
        sB  += __shfl_xor_sync(0xFFFFFFFFu, sB,  m);
        ssB += __shfl_xor_sync(0xFFFFFFFFu, ssB, m);
    }

    const float inv = 1.0f / 256.0f;
    const float muA = sA * inv;
    const float muB = sB * inv;
    const float varA = fmaf(-muA, muA, ssA * inv);
    const float varB = fmaf(-muB, muB, ssB * inv);
    const float rA = rsqrtf(varA + EPSV);
    const float rB = rsqrtf(varB + EPSV);

#pragma unroll
    for (int cc = 0; cc < 4; ++cc) {
#pragma unroll
        for (int r = 0; r < 2; ++r) {
            float4 q = v[cc * 2 + r];
            q.x = (q.x - muA) * rA;
            q.y = (q.y - muA) * rA;
            q.z = (q.z - muB) * rB;
            q.w = (q.w - muB) * rB;
            yb[base + cc * chanStride4 + r * 64] = q;
        }
    }
}

extern "C" void kernel_launch(void* const* d_in, const int* in_sizes, int n_in,
                              void* d_out, int out_size) {
    const float* x = (const float*)d_in[0];
    float* y = (float*)d_out;
    knorm2d_kernel<<<16 * 128 * 4, 256>>>(x, y);
}